// round 3
// baseline (speedup 1.0000x reference)
#include <cuda_runtime.h>

// realignment_layer: inputs (metadata order)
//   d_in[0] pcd_mis      float32 (32, 262144, 3)
//   d_in[1] T_mis        float32 (32, 4, 4)
//   d_in[2] delta_q_pred float32 (32, 4)
//   d_in[3] delta_t_pred float32 (32, 3)
// output: concat(batch_T_pred (32,4,4) -> 512 floats, pcd_new (32,262144,3))

static constexpr int B = 32;
static constexpr int NPTS = 262144;
static constexpr int FLOATS_PER_BATCH = NPTS * 3;          // 786432
static constexpr int THREADS = 256;
static constexpr int FLOATS_PER_THREAD = 12;               // 4 points
static constexpr int BLOCKS_PER_BATCH = FLOATS_PER_BATCH / (THREADS * FLOATS_PER_THREAD); // 256
static constexpr int TOTAL_BLOCKS = B * BLOCKS_PER_BATCH;  // 8192

// Closed-form inverse of [[R(q), t],[0,0,0,1]] with q normalized:
// invR = R^T, inv_t = -R^T t.  m is row-major 3x3 of invR.
__device__ __forceinline__ void compute_inv(const float* __restrict__ q,
                                            const float* __restrict__ t,
                                            float m[9], float it[3]) {
    float w = q[0], x = q[1], y = q[2], z = q[3];
    float s = rsqrtf(w * w + x * x + y * y + z * z);
    w *= s; x *= s; y *= s; z *= s;
    float r00 = 1.f - 2.f * (y * y + z * z);
    float r01 = 2.f * (x * y - z * w);
    float r02 = 2.f * (x * z + y * w);
    float r10 = 2.f * (x * y + z * w);
    float r11 = 1.f - 2.f * (x * x + z * z);
    float r12 = 2.f * (y * z - x * w);
    float r20 = 2.f * (x * z - y * w);
    float r21 = 2.f * (y * z + x * w);
    float r22 = 1.f - 2.f * (x * x + y * y);
    // invR = R^T
    m[0] = r00; m[1] = r10; m[2] = r20;
    m[3] = r01; m[4] = r11; m[5] = r21;
    m[6] = r02; m[7] = r12; m[8] = r22;
    float tx = t[0], ty = t[1], tz = t[2];
    it[0] = -(m[0] * tx + m[1] * ty + m[2] * tz);
    it[1] = -(m[3] * tx + m[4] * ty + m[5] * tz);
    it[2] = -(m[6] * tx + m[7] * ty + m[8] * tz);
}

// Kernel 1: batch_T_pred = inv_T @ T_mis.  32 blocks x 16 threads.
__global__ void tmat_kernel(const float* __restrict__ T_mis,
                            const float* __restrict__ q,
                            const float* __restrict__ t,
                            float* __restrict__ out) {
    int b = blockIdx.x;
    int tid = threadIdx.x;        // 0..15
    int i = tid >> 2;             // output row
    int k = tid & 3;              // output col

    float m[9], it[3];
    compute_inv(q + b * 4, t + b * 3, m, it);

    float row0, row1, row2, row3;
    if (i < 3) {
        row0 = m[i * 3 + 0]; row1 = m[i * 3 + 1]; row2 = m[i * 3 + 2]; row3 = it[i];
    } else {
        row0 = 0.f; row1 = 0.f; row2 = 0.f; row3 = 1.f;
    }
    const float* Tb = T_mis + b * 16;
    float s = row0 * Tb[0 * 4 + k] + row1 * Tb[1 * 4 + k]
            + row2 * Tb[2 * 4 + k] + row3 * Tb[3 * 4 + k];
    out[b * 16 + i * 4 + k] = s;
}

// Kernel 2: streaming point transform. Each thread: 4 points = 3 float4 in/out.
__global__ __launch_bounds__(THREADS)
void pcd_kernel(const float4* __restrict__ in,
                const float* __restrict__ q,
                const float* __restrict__ t,
                float4* __restrict__ out) {
    __shared__ float sm[12];
    int b = blockIdx.x >> 8;  // 256 blocks per batch

    if (threadIdx.x == 0) {
        float m[9], it[3];
        compute_inv(q + b * 4, t + b * 3, m, it);
        #pragma unroll
        for (int i = 0; i < 9; i++) sm[i] = m[i];
        sm[9] = it[0]; sm[10] = it[1]; sm[11] = it[2];
    }
    __syncthreads();

    const float m0 = sm[0], m1 = sm[1], m2 = sm[2];
    const float m3 = sm[3], m4 = sm[4], m5 = sm[5];
    const float m6 = sm[6], m7 = sm[7], m8 = sm[8];
    const float t0 = sm[9], t1 = sm[10], t2 = sm[11];

    size_t idx4 = ((size_t)blockIdx.x * THREADS + threadIdx.x) * 3;  // float4 units
    float4 v0 = in[idx4 + 0];
    float4 v1 = in[idx4 + 1];
    float4 v2 = in[idx4 + 2];

    // points: p0=(v0.x,v0.y,v0.z) p1=(v0.w,v1.x,v1.y) p2=(v1.z,v1.w,v2.x) p3=(v2.y,v2.z,v2.w)
    float ox0 = m0 * v0.x + m1 * v0.y + m2 * v0.z + t0;
    float oy0 = m3 * v0.x + m4 * v0.y + m5 * v0.z + t1;
    float oz0 = m6 * v0.x + m7 * v0.y + m8 * v0.z + t2;

    float ox1 = m0 * v0.w + m1 * v1.x + m2 * v1.y + t0;
    float oy1 = m3 * v0.w + m4 * v1.x + m5 * v1.y + t1;
    float oz1 = m6 * v0.w + m7 * v1.x + m8 * v1.y + t2;

    float ox2 = m0 * v1.z + m1 * v1.w + m2 * v2.x + t0;
    float oy2 = m3 * v1.z + m4 * v1.w + m5 * v2.x + t1;
    float oz2 = m6 * v1.z + m7 * v1.w + m8 * v2.x + t2;

    float ox3 = m0 * v2.y + m1 * v2.z + m2 * v2.w + t0;
    float oy3 = m3 * v2.y + m4 * v2.z + m5 * v2.w + t1;
    float oz3 = m6 * v2.y + m7 * v2.z + m8 * v2.w + t2;

    out[idx4 + 0] = make_float4(ox0, oy0, oz0, ox1);
    out[idx4 + 1] = make_float4(oy1, oz1, ox2, oy2);
    out[idx4 + 2] = make_float4(oz2, ox3, oy3, oz3);
}

extern "C" void kernel_launch(void* const* d_in, const int* in_sizes, int n_in,
                              void* d_out, int out_size) {
    const float* pcd   = (const float*)d_in[0];
    const float* T_mis = (const float*)d_in[1];
    const float* q     = (const float*)d_in[2];
    const float* t     = (const float*)d_in[3];
    float* out = (float*)d_out;

    (void)in_sizes; (void)n_in; (void)out_size;

    // batch_T_pred -> out[0..511]
    tmat_kernel<<<B, 16>>>(T_mis, q, t, out);
    // pcd_new -> out[512..]
    pcd_kernel<<<TOTAL_BLOCKS, THREADS>>>((const float4*)pcd, q, t,
                                          (float4*)(out + B * 16));
}